// round 8
// baseline (speedup 1.0000x reference)
#include <cuda_runtime.h>

// Problem constants
#define NB 4
#define NC 8
#define NF 512
#define NT 1000
#define NPAIR 36   // upper triangle incl diagonal of 8x8

// Scratch: per-(b,f) 8x8 complex filter G[m*8+c] = conj(W[c][m])
__device__ float2 g_G[NB * NF * 64];

static __device__ __forceinline__ float2 cmul(float2 a, float2 b) {
    return make_float2(a.x * b.x - a.y * b.y, a.x * b.y + a.y * b.x);
}

static __device__ __forceinline__ float warp_reduce(float v) {
    #pragma unroll
    for (int o = 16; o; o >>= 1) v += __shfl_down_sync(0xffffffffu, v, o);
    return v;
}

// PSD accumulation for pair-group G: rows R0=G and R1=7-G of the upper
// triangle (9 pairs). Raw-mask weighted; products shared across both masks.
// Warp covers t in [half*500, half*500+500) as 125 float4 groups.
template <int G, bool SUMS>
static __device__ __forceinline__ void psd_group_v2(
    const float* __restrict__ xre, const float* __restrict__ xim,
    const float* __restrict__ ms,  const float* __restrict__ mn,
    long xbase, long mbase,
    float* bufr0, float* bufr1, float* bufi0, float* bufi1,
    float* sums, int half, int lane)
{
    constexpr int R0 = G;
    constexpr int R1 = 7 - G;
    constexpr int N0 = 8 - G;       // pairs in row R0
    constexpr int BASE0 = 8 * R0 - (R0 * (R0 - 1)) / 2;
    constexpr int BASE1 = 8 * R1 - (R1 * (R1 - 1)) / 2;

    float aR[2][9], aI[2][9];
    #pragma unroll
    for (int k = 0; k < 9; k++) {
        aR[0][k] = 0.f; aR[1][k] = 0.f; aI[0][k] = 0.f; aI[1][k] = 0.f;
    }
    float ssum = 0.f, nsum = 0.f;

    const int qbase = half * 125;
    #pragma unroll
    for (int it = 0; it < 4; it++) {
        int q = lane + (it << 5);
        if (q < 125) {
            long t0 = (long)(qbase + q) * 4;
            float4 ms4 = *reinterpret_cast<const float4*>(ms + mbase + t0);
            float4 mn4 = *reinterpret_cast<const float4*>(mn + mbase + t0);
            if (SUMS) {
                ssum += (ms4.x + ms4.y) + (ms4.z + ms4.w);
                nsum += (mn4.x + mn4.y) + (mn4.z + mn4.w);
            }
            float msv[4] = { ms4.x, ms4.y, ms4.z, ms4.w };
            float mnv[4] = { mn4.x, mn4.y, mn4.z, mn4.w };

            float a0r[4], a0i[4], a1r[4], a1i[4];
            #pragma unroll
            for (int kk = 0; kk < 8 - G; kk++) {
                const int c = R0 + kk;
                long g = xbase + (long)c * (NF * NT) + t0;
                float4 br4 = *reinterpret_cast<const float4*>(xre + g);
                float4 bi4 = *reinterpret_cast<const float4*>(xim + g);
                float br[4] = { br4.x, br4.y, br4.z, br4.w };
                float bi[4] = { bi4.x, bi4.y, bi4.z, bi4.w };
                if (c == R0) {
                    #pragma unroll
                    for (int j = 0; j < 4; j++) { a0r[j] = br[j]; a0i[j] = bi[j]; }
                }
                if (c == R1) {
                    #pragma unroll
                    for (int j = 0; j < 4; j++) { a1r[j] = br[j]; a1i[j] = bi[j]; }
                }
                // pair (R0, c):  x_{R0} * conj(x_c)
                {
                    const int k0 = kk;
                    #pragma unroll
                    for (int j = 0; j < 4; j++) {
                        float pr = a0r[j] * br[j] + a0i[j] * bi[j];
                        float pi = a0i[j] * br[j] - a0r[j] * bi[j];
                        aR[0][k0] += msv[j] * pr; aR[1][k0] += mnv[j] * pr;
                        aI[0][k0] += msv[j] * pi; aI[1][k0] += mnv[j] * pi;
                    }
                }
                // pair (R1, c) for c >= R1:  x_{R1} * conj(x_c)
                if (c >= R1) {
                    const int k1 = N0 + (c - R1);
                    #pragma unroll
                    for (int j = 0; j < 4; j++) {
                        float pr = a1r[j] * br[j] + a1i[j] * bi[j];
                        float pi = a1i[j] * br[j] - a1r[j] * bi[j];
                        aR[0][k1] += msv[j] * pr; aR[1][k1] += mnv[j] * pr;
                        aI[0][k1] += msv[j] * pi; aI[1][k1] += mnv[j] * pi;
                    }
                }
            }
        }
    }

    #pragma unroll
    for (int k = 0; k < 9; k++) {
        float r0 = warp_reduce(aR[0][k]);
        float r1 = warp_reduce(aR[1][k]);
        float i0 = warp_reduce(aI[0][k]);
        float i1 = warp_reduce(aI[1][k]);
        if (lane == 0) {
            int p = (k < N0) ? (BASE0 + k) : (BASE1 + (k - N0));
            atomicAdd(bufr0 + p, r0);
            atomicAdd(bufr1 + p, r1);
            atomicAdd(bufi0 + p, i0);
            atomicAdd(bufi1 + p, i1);
        }
    }
    if (SUMS) {
        ssum = warp_reduce(ssum);
        nsum = warp_reduce(nsum);
        if (lane == 0) { atomicAdd(&sums[0], ssum); atomicAdd(&sums[1], nsum); }
    }
}

// ---------------------------------------------------------------------------
// Kernel 1: masked PSDs + diag-reg + Gauss-Jordan solve -> G into g_G
// ---------------------------------------------------------------------------
__global__ __launch_bounds__(256, 2)
void psd_solve_kernel(const float* __restrict__ xre, const float* __restrict__ xim,
                      const float* __restrict__ ms,  const float* __restrict__ mn)
{
    __shared__ float  bufr[2][NPAIR];
    __shared__ float  bufi[2][NPAIR];
    __shared__ float2 A[64];
    __shared__ float2 Bm[64];
    __shared__ float  sums[2];
    __shared__ float  invf[2];   // 1/(sum+eps) for s, n
    __shared__ float  dreg;
    __shared__ float2 pivinv;
    __shared__ float2 winv;

    const int tid = threadIdx.x;
    const int bf  = blockIdx.x;
    const int b   = bf / NF;
    const int f   = bf - b * NF;

    if (tid < NPAIR) {
        bufr[0][tid] = 0.f; bufi[0][tid] = 0.f;
        bufr[1][tid] = 0.f; bufi[1][tid] = 0.f;
    }
    if (tid == 64) { sums[0] = 0.f; sums[1] = 0.f; }
    __syncthreads();

    // PSD: 8 warps = 2 t-halves x 4 pair-groups; raw-mask accumulation
    {
        const int w    = tid >> 5;
        const int lane = tid & 31;
        const int half = w & 1;
        const long xbase = ((long)b * NC) * NF * NT + (long)f * NT;
        const long mbase = ((long)b * NF + f) * NT;
        switch (w >> 1) {
            case 0: psd_group_v2<0, true >(xre, xim, ms, mn, xbase, mbase, bufr[0], bufr[1], bufi[0], bufi[1], sums, half, lane); break;
            case 1: psd_group_v2<1, false>(xre, xim, ms, mn, xbase, mbase, bufr[0], bufr[1], bufi[0], bufi[1], sums, half, lane); break;
            case 2: psd_group_v2<2, false>(xre, xim, ms, mn, xbase, mbase, bufr[0], bufr[1], bufi[0], bufi[1], sums, half, lane); break;
            default: psd_group_v2<3, false>(xre, xim, ms, mn, xbase, mbase, bufr[0], bufr[1], bufi[0], bufi[1], sums, half, lane); break;
        }
    }
    __syncthreads();

    // normalization factors + diag regularizer (on normalized psd_n)
    if (tid == 0) {
        float is = 1.f / (sums[0] + 1e-10f);
        float in = 1.f / (sums[1] + 1e-10f);
        invf[0] = is; invf[1] = in;
        float trn = 0.f;
        #pragma unroll
        for (int c = 0; c < NC; c++) trn += bufr[1][8 * c - (c * (c - 1)) / 2];
        dreg = 1e-6f * trn * in + 1e-8f;
    }
    __syncthreads();

    // build full Hermitian A (psd_n + d I) and Bm (psd_s), applying 1/sum
    if (tid < 64) {
        int i = tid >> 3, j = tid & 7;
        int lo = i < j ? i : j;
        int hi = i < j ? j : i;
        int p = 8 * lo - (lo * (lo - 1)) / 2 + (hi - lo);
        float sgn = (i <= j) ? 1.f : -1.f;
        float is = invf[0], in = invf[1];
        float2 an = make_float2(in * bufr[1][p], sgn * in * bufi[1][p]);
        float2 as = make_float2(is * bufr[0][p], sgn * is * bufi[0][p]);
        if (i == j) an.x += dreg;
        A[tid]  = an;
        Bm[tid] = as;
    }
    __syncthreads();

    // Gauss-Jordan: A X = Bm  ->  Bm = X
    {
        int i = tid >> 3, j = tid & 7;
        for (int k = 0; k < 8; k++) {
            if (tid == 0) {
                float2 pv = A[k * 8 + k];
                float d = pv.x * pv.x + pv.y * pv.y;
                pivinv = make_float2(pv.x / d, -pv.y / d);
            }
            __syncthreads();
            if (tid < 64 && i == k) {
                float2 pin = pivinv;
                A[tid]  = cmul(A[tid], pin);
                Bm[tid] = cmul(Bm[tid], pin);
            }
            __syncthreads();
            float2 fct, akj, bkj;
            bool act = (tid < 64) && (i != k);
            if (act) { fct = A[i * 8 + k]; akj = A[k * 8 + j]; bkj = Bm[k * 8 + j]; }
            __syncthreads();
            if (act) {
                float2 a = A[tid], bm = Bm[tid];
                a.x  -= fct.x * akj.x - fct.y * akj.y;
                a.y  -= fct.x * akj.y + fct.y * akj.x;
                bm.x -= fct.x * bkj.x - fct.y * bkj.y;
                bm.y -= fct.x * bkj.y + fct.y * bkj.x;
                A[tid] = a; Bm[tid] = bm;
            }
            __syncthreads();
        }
    }

    // W = X / (beta + tr X); G[m*8+c] = conj(W[c][m]) -> gmem scratch
    if (tid == 0) {
        float2 tr = make_float2(1.0f, 0.0f);  // beta = 1
        #pragma unroll
        for (int c = 0; c < NC; c++) { tr.x += Bm[c * 8 + c].x; tr.y += Bm[c * 8 + c].y; }
        float d = tr.x * tr.x + tr.y * tr.y;
        winv = make_float2(tr.x / d, -tr.y / d);
    }
    __syncthreads();
    if (tid < 64) {
        int i = tid >> 3, j = tid & 7;      // i = c, j = m
        float2 w = cmul(Bm[tid], winv);
        g_G[bf * 64 + j * 8 + i] = make_float2(w.x, -w.y);
    }
}

// ---------------------------------------------------------------------------
// Kernel 2: streaming filter  out[m][t] = sum_c G[m][c] * x[c][t]
// ---------------------------------------------------------------------------
template <bool COMPLEX_OUT>
__global__ __launch_bounds__(256, 4)
void filter_kernel(const float* __restrict__ xre, const float* __restrict__ xim,
                   float* __restrict__ out)
{
    __shared__ float2 Gs[64];
    const int tid = threadIdx.x;
    const int bf  = blockIdx.x;
    const int b   = bf / NF;
    const int f   = bf - b * NF;

    if (tid < 64) Gs[tid] = g_G[bf * 64 + tid];
    __syncthreads();
    if (tid >= 250) return;

    const int t0 = tid * 4;
    const long base = ((long)b * NC) * NF * NT + (long)f * NT;

    if (!COMPLEX_OUT) {
        float acc[8][4] = {};
        #pragma unroll
        for (int c = 0; c < NC; c++) {
            long g = base + (long)c * NF * NT + t0;
            float4 r  = *reinterpret_cast<const float4*>(xre + g);
            float4 im = *reinterpret_cast<const float4*>(xim + g);
            float xr[4] = { r.x, r.y, r.z, r.w };
            float xi[4] = { im.x, im.y, im.z, im.w };
            #pragma unroll
            for (int m = 0; m < 8; m++) {
                float2 gg = Gs[m * 8 + c];
                #pragma unroll
                for (int j = 0; j < 4; j++)
                    acc[m][j] += gg.x * xr[j] - gg.y * xi[j];
            }
        }
        #pragma unroll
        for (int m = 0; m < 8; m++)
            *reinterpret_cast<float4*>(out + base + (long)m * NF * NT + t0) =
                make_float4(acc[m][0], acc[m][1], acc[m][2], acc[m][3]);
    } else {
        #pragma unroll
        for (int mh = 0; mh < 8; mh += 4) {
            float2 acc[4][4];
            #pragma unroll
            for (int mi = 0; mi < 4; mi++)
                #pragma unroll
                for (int j = 0; j < 4; j++) acc[mi][j] = make_float2(0.f, 0.f);
            #pragma unroll
            for (int c = 0; c < NC; c++) {
                long g = base + (long)c * NF * NT + t0;
                float4 r  = *reinterpret_cast<const float4*>(xre + g);
                float4 im = *reinterpret_cast<const float4*>(xim + g);
                float xr[4] = { r.x, r.y, r.z, r.w };
                float xi[4] = { im.x, im.y, im.z, im.w };
                #pragma unroll
                for (int mi = 0; mi < 4; mi++) {
                    float2 gg = Gs[(mh + mi) * 8 + c];
                    #pragma unroll
                    for (int j = 0; j < 4; j++) {
                        acc[mi][j].x += gg.x * xr[j] - gg.y * xi[j];
                        acc[mi][j].y += gg.x * xi[j] + gg.y * xr[j];
                    }
                }
            }
            #pragma unroll
            for (int mi = 0; mi < 4; mi++) {
                float2* op = reinterpret_cast<float2*>(out) + base + (long)(mh + mi) * NF * NT + t0;
                float4* op4 = reinterpret_cast<float4*>(op);
                op4[0] = make_float4(acc[mi][0].x, acc[mi][0].y, acc[mi][1].x, acc[mi][1].y);
                op4[1] = make_float4(acc[mi][2].x, acc[mi][2].y, acc[mi][3].x, acc[mi][3].y);
            }
        }
    }
}

extern "C" void kernel_launch(void* const* d_in, const int* in_sizes, int n_in,
                              void* d_out, int out_size) {
    (void)in_sizes; (void)n_in;
    const float* xre = (const float*)d_in[0];
    const float* xim = (const float*)d_in[1];
    const float* ms  = (const float*)d_in[2];
    const float* mn  = (const float*)d_in[3];
    const int nElem = NB * NC * NF * NT;
    const bool cplx = (out_size >= 2 * nElem);

    psd_solve_kernel<<<NB * NF, 256>>>(xre, xim, ms, mn);
    if (cplx)
        filter_kernel<true><<<NB * NF, 256>>>(xre, xim, (float*)d_out);
    else
        filter_kernel<false><<<NB * NF, 256>>>(xre, xim, (float*)d_out);
}